// round 3
// baseline (speedup 1.0000x reference)
#include <cuda_runtime.h>

// DepthWiseConv1d: inputs [B=32, C=128, L=8192] fp32, weight [C,3], bias [C]
// out[b,c,l] = w0*x[l-1] + w1*x[l] + w2*x[l+1] + bias   (zero pad)
//
// Pure HBM-streaming kernel: one block per (b,c) row, float4 everywhere,
// halo via 2 predicated scalar L1-hit loads per float4 group.

#define CONV_L    8192
#define CONV_C    128
#define CONV_TPB  256
#define CONV_ITER (CONV_L / 4 / CONV_TPB)   // 8 float4 groups per thread

__global__ void __launch_bounds__(CONV_TPB)
DepthWiseConv1d_23364622090654_kernel(const float* __restrict__ x,
                                      const float* __restrict__ w,
                                      const float* __restrict__ b,
                                      float* __restrict__ out)
{
    const int row = blockIdx.x;              // 0 .. B*C-1
    const int c   = row & (CONV_C - 1);

    const float w0   = __ldg(&w[c * 3 + 0]);
    const float w1   = __ldg(&w[c * 3 + 1]);
    const float w2   = __ldg(&w[c * 3 + 2]);
    const float bias = __ldg(&b[c]);

    const float* __restrict__ xr = x   + (size_t)row * CONV_L;
    float*       __restrict__ orw = out + (size_t)row * CONV_L;

    const int t = threadIdx.x;

    // Phase 1: batch all loads (max MLP; 24 independent loads in flight).
    float4 v[CONV_ITER];
    float  lft[CONV_ITER], rgt[CONV_ITER];
    #pragma unroll
    for (int k = 0; k < CONV_ITER; k++) {
        const int p = (t + k * CONV_TPB) * 4;          // warp-coalesced
        v[k]   = *reinterpret_cast<const float4*>(xr + p);
        lft[k] = (p == 0)          ? 0.0f : __ldg(xr + p - 1);   // L1-hit
        rgt[k] = (p + 4 == CONV_L) ? 0.0f : __ldg(xr + p + 4);   // L1-hit
    }

    // Phase 2: compute + coalesced float4 stores.
    #pragma unroll
    for (int k = 0; k < CONV_ITER; k++) {
        const int p = (t + k * CONV_TPB) * 4;
        float4 o;
        o.x = fmaf(w0, lft[k],  fmaf(w1, v[k].x, fmaf(w2, v[k].y, bias)));
        o.y = fmaf(w0, v[k].x,  fmaf(w1, v[k].y, fmaf(w2, v[k].z, bias)));
        o.z = fmaf(w0, v[k].y,  fmaf(w1, v[k].z, fmaf(w2, v[k].w, bias)));
        o.w = fmaf(w0, v[k].z,  fmaf(w1, v[k].w, fmaf(w2, rgt[k], bias)));
        *reinterpret_cast<float4*>(orw + p) = o;
    }
}

extern "C" void kernel_launch(void* const* d_in, const int* in_sizes, int n_in,
                              void* d_out, int out_size)
{
    const float* x = (const float*)d_in[0];   // inputs  [B,C,L]
    const float* w = (const float*)d_in[1];   // weight  [C,3]
    const float* b = (const float*)d_in[2];   // bias    [C]
    float* out = (float*)d_out;

    const int rows = in_sizes[0] / CONV_L;    // B*C = 4096

    DepthWiseConv1d_23364622090654_kernel<<<rows, CONV_TPB>>>(x, w, b, out);
}

// round 4
// speedup vs baseline: 1.0285x; 1.0285x over previous
#include <cuda_runtime.h>

// DepthWiseConv1d: inputs [B=32, C=128, L=8192] fp32, weight [C,3], bias [C]
// out[b,c,l] = w0*x[l-1] + w1*x[l] + w2*x[l+1] + bias   (zero pad)
//
// HBM-streaming kernel, occupancy-first variant:
//  - one block per 2048-element chunk of a row (chunks never cross rows)
//  - 2 float4 groups per thread -> ~30 regs -> 8 blocks/SM resident
//  - halo via 2 predicated scalar loads per group (L1/L2 hits)
//  - streaming store hint (__stcs): output is never re-read

#define CONV_L     8192
#define CONV_C     128
#define CONV_TPB   256
#define CONV_CHUNK 2048                          // elements per block
#define CONV_ITER  (CONV_CHUNK / 4 / CONV_TPB)   // 2 float4 groups per thread

__global__ void __launch_bounds__(CONV_TPB)
DepthWiseConv1d_23364622090654_kernel(const float* __restrict__ x,
                                      const float* __restrict__ w,
                                      const float* __restrict__ b,
                                      float* __restrict__ out)
{
    const size_t base = (size_t)blockIdx.x * CONV_CHUNK;
    const int c = (int)((base >> 13) & (CONV_C - 1));   // channel of this row

    const float w0   = __ldg(&w[c * 3 + 0]);
    const float w1   = __ldg(&w[c * 3 + 1]);
    const float w2   = __ldg(&w[c * 3 + 2]);
    const float bias = __ldg(&b[c]);

    const int t = threadIdx.x;

    float4 v[CONV_ITER];
    float  lft[CONV_ITER], rgt[CONV_ITER];

    #pragma unroll
    for (int k = 0; k < CONV_ITER; k++) {
        const size_t gp  = base + (size_t)(t + k * CONV_TPB) * 4;  // warp-coalesced
        const int    pos = (int)(gp & (CONV_L - 1));               // position in row
        v[k]   = *reinterpret_cast<const float4*>(x + gp);
        lft[k] = (pos == 0)              ? 0.0f : __ldg(x + gp - 1);  // L1/L2 hit
        rgt[k] = (pos + 4 == CONV_L)     ? 0.0f : __ldg(x + gp + 4);  // L1/L2 hit
    }

    #pragma unroll
    for (int k = 0; k < CONV_ITER; k++) {
        const size_t gp = base + (size_t)(t + k * CONV_TPB) * 4;
        float4 o;
        o.x = fmaf(w0, lft[k],  fmaf(w1, v[k].x, fmaf(w2, v[k].y, bias)));
        o.y = fmaf(w0, v[k].x,  fmaf(w1, v[k].y, fmaf(w2, v[k].z, bias)));
        o.z = fmaf(w0, v[k].y,  fmaf(w1, v[k].z, fmaf(w2, v[k].w, bias)));
        o.w = fmaf(w0, v[k].z,  fmaf(w1, v[k].w, fmaf(w2, rgt[k], bias)));
        __stcs(reinterpret_cast<float4*>(out + gp), o);   // streaming store
    }
}

extern "C" void kernel_launch(void* const* d_in, const int* in_sizes, int n_in,
                              void* d_out, int out_size)
{
    const float* x = (const float*)d_in[0];   // inputs  [B,C,L]
    const float* w = (const float*)d_in[1];   // weight  [C,3]
    const float* b = (const float*)d_in[2];   // bias    [C]
    float* out = (float*)d_out;

    const int rows   = in_sizes[0] / CONV_L;              // B*C = 4096
    const int blocks = rows * (CONV_L / CONV_CHUNK);      // 16384

    DepthWiseConv1d_23364622090654_kernel<<<blocks, CONV_TPB>>>(x, w, b, out);
}